// round 14
// baseline (speedup 1.0000x reference)
#include <cuda_runtime.h>
#include <stdint.h>

// Fixed-shape bench: N=2e6 points, C=64 floats, bs=8, max_length=out/(8*64).
#define NBINS      8
#define THREADS    256
#define PPB        1792                 // points per block -> grid fills 8 CTA/SM
#define ITEMS      (PPB / THREADS)      // 7 contiguous points per thread
#define MAX_BLOCKS 8192
#define ZBLOCKS    64                   // tail-zero tickets
#define FULLMASK   0xFFFFFFFFu
#define PF_LINES   512                  // 64KB/block (~74MB chip-wide): measured optimum

// Persistent scratch — never reset. Epoch-tagged: 32-bit ticket increases
// monotonically; epoch = ticket / gridTotal; all waits compare >= epoch+1,
// so stale values from earlier replays are strictly smaller.
__device__ unsigned g_ticket;                    // zero-init at load
__device__ unsigned g_flag[MAX_BLOCKS];          // epoch+1 when block agg ready
__device__ int      g_agg [MAX_BLOCKS * NBINS];
__device__ int      g_excl[MAX_BLOCKS * NBINS];  // per-block per-bin exclusive base
__device__ unsigned g_scanDone;                  // epoch+1 when g_excl ready
__device__ unsigned g_totFlag;                   // epoch+1 when totals ready
__device__ int      g_totals[NBINS];

// ---------------------------------------------------------------------------
// Single launch, three roles by ticket:
//   vbid <  nblocks                : scatter block (publish agg, wait, copy)
//   nblocks <= vbid < nblocks+ZB   : tail-zero block
//   vbid == nblocks+ZB (last)      : scanner (global 8-bin exclusive scan)
// Whole grid resident in one wave: grid=1182 <= 8 CTA/SM * 148 SMs = 1184
// (152 SMs on GB300 -> 1216), launch_bounds pins regs<=32.
// While warp 0 waits on the scanner, warps 1-7 prefetch the head of the
// block's feat chunk into L2. R14 change (only): output stores in the copy
// loop use __stcs (evict-first) so the write-once output stream does not
// displace prefetched feat lines in L2. Loads remain default (R5 showed
// __ldcs on feat is harmful — it demotes the lines prefetch protects).
// ---------------------------------------------------------------------------
__global__ __launch_bounds__(THREADS, 8)
void fused_kernel(const int4* __restrict__ inds4,
                  const float4* __restrict__ feat,
                  float4* __restrict__ out,
                  int n, int max_length, int nblocks, int gridTotal) {
    __shared__ unsigned s_ticket;
    __shared__ uint8_t  s_b[PPB];
    __shared__ int      s_dst[PPB];
    __shared__ uint32_t s_wtot[THREADS / 32][4];   // warp-inclusive totals (packed)
    __shared__ uint32_t s_wexc[THREADS / 32][4];   // warp exclusive offsets
    __shared__ int      s_off[NBINS];              // this block's per-bin base

    int tid  = threadIdx.x;
    int wid  = tid >> 5;
    int lane = tid & 31;

    if (tid == 0) s_ticket = atomicAdd(&g_ticket, 1u);
    __syncthreads();
    unsigned t     = s_ticket;
    unsigned epoch = t / (unsigned)gridTotal;
    int      vbid  = (int)(t - epoch * (unsigned)gridTotal);
    unsigned etag  = epoch + 1u;

    // ---- scanner ticket (last) --------------------------------------------
    if (vbid == nblocks + ZBLOCKS) {
        for (int blk = tid; blk < nblocks; blk += THREADS)
            while (*(volatile unsigned*)&g_flag[blk] < etag) { }
        __syncthreads();
        __threadfence();
        if (wid < NBINS) {
            int bin = wid;
            int per = (nblocks + 31) / 32;
            int lo  = lane * per;
            int hi  = min(lo + per, nblocks);
            int sum = 0;
            for (int blk = lo; blk < hi; blk++)
                sum += g_agg[blk * NBINS + bin];
            int v = sum;
#pragma unroll
            for (int off = 1; off < 32; off <<= 1) {
                int tt = __shfl_up_sync(FULLMASK, v, off);
                if (lane >= off) v += tt;
            }
            int run = v - sum;                       // exclusive chunk base
            for (int blk = lo; blk < hi; blk++) {
                g_excl[blk * NBINS + bin] = run;
                run += g_agg[blk * NBINS + bin];
            }
            int tot = __shfl_sync(FULLMASK, v, 31);  // bin total
            if (lane == 0) g_totals[bin] = tot;
        }
        __syncthreads();
        __threadfence();
        if (tid == 0) {
            *(volatile unsigned*)&g_totFlag  = etag;
            *(volatile unsigned*)&g_scanDone = etag;
        }
        return;
    }

    // ---- tail-zero tickets -------------------------------------------------
    if (vbid >= nblocks) {
        if (tid == 0) {
            while (*(volatile unsigned*)&g_totFlag < etag) { }
        }
        __syncthreads();
        __threadfence();
        int z   = vbid - nblocks;            // 0..ZBLOCKS-1
        int bin = z >> 3;                    // 8 tickets per bin
        int sub = z & 7;
        int c   = min(g_totals[bin], max_length);
        size_t start  = ((size_t)bin * max_length + c) * 16;
        size_t end    = ((size_t)(bin + 1) * max_length) * 16;
        size_t stride = (size_t)8 * THREADS;
        float4 zf = make_float4(0.f, 0.f, 0.f, 0.f);
        for (size_t i = start + (size_t)sub * THREADS + tid; i < end; i += stride)
            out[i] = zf;
        return;
    }

    // ---- scatter tickets ---------------------------------------------------
    int base = vbid * PPB;
    int cnt  = min(PPB, n - base);

    // coalesced load of b values into smem (only read of inds)
    for (int j = tid; j < cnt; j += THREADS)
        s_b[j] = (uint8_t)(inds4[base + j].x & (NBINS - 1));
    __syncthreads();

    // per-thread packed counts over contiguous ITEMS (2 bins / word, 16-bit)
    uint32_t c[4] = {0, 0, 0, 0};
    int lo = tid * ITEMS;
#pragma unroll
    for (int k = 0; k < ITEMS; k++) {
        int j = lo + k;
        if (j < cnt) {
            int b = s_b[j];
            c[b >> 1] += (1u << ((b & 1) * 16));
        }
    }

    // warp-level inclusive scan of the packed vector
    uint32_t inc[4];
#pragma unroll
    for (int i = 0; i < 4; i++) inc[i] = c[i];
#pragma unroll
    for (int off = 1; off < 32; off <<= 1) {
#pragma unroll
        for (int i = 0; i < 4; i++) {
            uint32_t v = __shfl_up_sync(FULLMASK, inc[i], off);
            if (lane >= off) inc[i] += v;
        }
    }
    if (lane == 31) {
#pragma unroll
        for (int i = 0; i < 4; i++) s_wtot[wid][i] = inc[i];
    }
    __syncthreads();

    if (wid == 0) {
        // ---- warp 0: publish aggregate, inter-warp scan, wait for scanner --
        int agg = 0;
        if (lane < NBINS) {
            int w4 = lane >> 1, sh = (lane & 1) * 16;
#pragma unroll
            for (int w = 0; w < THREADS / 32; w++)
                agg += (int)((s_wtot[w][w4] >> sh) & 0xFFFFu);
        }
        if (lane < NBINS) g_agg[vbid * NBINS + lane] = agg;
        __threadfence();
        if (lane == 0) *(volatile unsigned*)&g_flag[vbid] = etag;

        // inter-warp exclusive scan of warp totals (overlaps the spin wait)
        {
            int word = lane >> 3;
            int w    = lane & 7;
            uint32_t orig = s_wtot[w][word];
            uint32_t v = orig;
#pragma unroll
            for (int off = 1; off < 8; off <<= 1) {
                uint32_t tt = __shfl_up_sync(FULLMASK, v, off);
                if ((lane & 7) >= off) v += tt;
            }
            s_wexc[w][word] = v - orig;
        }

        // wait for the global scan, then fetch this block's bases
        if (lane == 0) {
            while (*(volatile unsigned*)&g_scanDone < etag) { }
        }
        __syncwarp();
        __threadfence();
        if (lane < NBINS) s_off[lane] = g_excl[vbid * NBINS + lane];
    } else {
        // ---- warps 1-7: prefetch head of feat chunk into L2 while waiting --
        // Descending line order => first-used lines are most recently touched.
        const char* chunk = (const char*)(feat + (size_t)base * 16);
        int pt = tid - 32;                       // 0..223
        int maxLines = min(PF_LINES, (cnt * 16) / 8);   // 128B lines in chunk
        for (int i = maxLines - 1 - pt; i >= 0; i -= (THREADS - 32)) {
            asm volatile("prefetch.global.L2 [%0];" :: "l"(chunk + (size_t)i * 128));
        }
    }
    __syncthreads();

    // exclusive prefix for this thread
    uint32_t p[4];
#pragma unroll
    for (int i = 0; i < 4; i++) p[i] = inc[i] - c[i] + s_wexc[wid][i];

    // replay: assign stable ranks, compute destination rows
#pragma unroll
    for (int k = 0; k < ITEMS; k++) {
        int j = lo + k;
        if (j < cnt) {
            int b   = s_b[j];
            int sh  = (b & 1) * 16;
            int w   = b >> 1;
            int pos = s_off[b] + (int)((p[w] >> sh) & 0xFFFFu);
            p[w] += (1u << sh);
            s_dst[j] = (pos < max_length) ? (b * max_length + pos) : -1;
        }
    }
    __syncthreads();

    // cooperative copy: 16 threads per point, one float4 lane each (256B rows).
    // Stores are evict-first (__stcs): write-once stream must not displace
    // prefetched feat lines in L2. Loads stay default.
    int group = tid >> 4;
    int flane = tid & 15;
#pragma unroll 4
    for (int j = group; j < cnt; j += 16) {
        int d = s_dst[j];
        float4 v = feat[(size_t)(base + j) * 16 + flane];
        if (d >= 0)
            __stcs(&out[(size_t)d * 16 + flane], v);
    }
}

// ---------------------------------------------------------------------------
extern "C" void kernel_launch(void* const* d_in, const int* in_sizes, int n_in,
                              void* d_out, int out_size) {
    const int4*   inds4 = (const int4*)d_in[0];
    const float4* feat  = (const float4*)d_in[1];
    float4*       out   = (float4*)d_out;

    int n = in_sizes[0] / 4;                  // points (inds is [N,4])
    int C = in_sizes[1] / n;                  // 64
    int max_length = out_size / (NBINS * C);  // 256000

    int nblocks = (n + PPB - 1) / PPB;        // 1117
    if (nblocks > MAX_BLOCKS) nblocks = MAX_BLOCKS;
    int gridTotal = nblocks + ZBLOCKS + 1;    // 1182 (scatter + zero + scanner)

    fused_kernel<<<gridTotal, THREADS>>>(inds4, feat, out,
                                         n, max_length, nblocks, gridTotal);
}

// round 15
// speedup vs baseline: 1.0044x; 1.0044x over previous
#include <cuda_runtime.h>
#include <stdint.h>

// Fixed-shape bench: N=2e6 points, C=64 floats, bs=8, max_length=out/(8*64).
#define NBINS      8
#define THREADS    256
#define PPB        1792                 // points per block -> grid fills 8 CTA/SM
#define ITEMS      (PPB / THREADS)      // 7 contiguous points per thread
#define MAX_BLOCKS 8192
#define ZBLOCKS    64                   // tail-zero tickets
#define FULLMASK   0xFFFFFFFFu
#define PF_LINES   512                  // 64KB/block (~74MB chip-wide): measured optimum; 640 thrashes L2

// Persistent scratch — never reset. Epoch-tagged: 32-bit ticket increases
// monotonically; epoch = ticket / gridTotal; all waits compare >= epoch+1,
// so stale values from earlier replays are strictly smaller.
__device__ unsigned g_ticket;                    // zero-init at load
__device__ unsigned g_flag[MAX_BLOCKS];          // epoch+1 when block agg ready
__device__ int      g_agg [MAX_BLOCKS * NBINS];
__device__ int      g_excl[MAX_BLOCKS * NBINS];  // per-block per-bin exclusive base
__device__ unsigned g_scanDone;                  // epoch+1 when g_excl ready
__device__ unsigned g_totFlag;                   // epoch+1 when totals ready
__device__ int      g_totals[NBINS];

// ---------------------------------------------------------------------------
// Single launch, three roles by ticket:
//   vbid <  nblocks                : scatter block (publish agg, wait, copy)
//   nblocks <= vbid < nblocks+ZB   : tail-zero block
//   vbid == nblocks+ZB (last)      : scanner (global 8-bin exclusive scan)
// Whole grid resident in one wave: grid=1182 <= 8 CTA/SM * 148 SMs = 1184
// (152 SMs on GB300 -> 1216), launch_bounds pins regs<=32.
// While warp 0 waits on the scanner, warps 1-7 prefetch the head of the
// block's feat chunk into L2 (descending order; LRU keeps first-used lines),
// converting the otherwise DRAM-idle scan window into useful read traffic.
// ---------------------------------------------------------------------------
__global__ __launch_bounds__(THREADS, 8)
void fused_kernel(const int4* __restrict__ inds4,
                  const float4* __restrict__ feat,
                  float4* __restrict__ out,
                  int n, int max_length, int nblocks, int gridTotal) {
    __shared__ unsigned s_ticket;
    __shared__ uint8_t  s_b[PPB];
    __shared__ int      s_dst[PPB];
    __shared__ uint32_t s_wtot[THREADS / 32][4];   // warp-inclusive totals (packed)
    __shared__ uint32_t s_wexc[THREADS / 32][4];   // warp exclusive offsets
    __shared__ int      s_off[NBINS];              // this block's per-bin base

    int tid  = threadIdx.x;
    int wid  = tid >> 5;
    int lane = tid & 31;

    if (tid == 0) s_ticket = atomicAdd(&g_ticket, 1u);
    __syncthreads();
    unsigned t     = s_ticket;
    unsigned epoch = t / (unsigned)gridTotal;
    int      vbid  = (int)(t - epoch * (unsigned)gridTotal);
    unsigned etag  = epoch + 1u;

    // ---- scanner ticket (last) --------------------------------------------
    if (vbid == nblocks + ZBLOCKS) {
        for (int blk = tid; blk < nblocks; blk += THREADS)
            while (*(volatile unsigned*)&g_flag[blk] < etag) { }
        __syncthreads();
        __threadfence();
        if (wid < NBINS) {
            int bin = wid;
            int per = (nblocks + 31) / 32;
            int lo  = lane * per;
            int hi  = min(lo + per, nblocks);
            int sum = 0;
            for (int blk = lo; blk < hi; blk++)
                sum += g_agg[blk * NBINS + bin];
            int v = sum;
#pragma unroll
            for (int off = 1; off < 32; off <<= 1) {
                int tt = __shfl_up_sync(FULLMASK, v, off);
                if (lane >= off) v += tt;
            }
            int run = v - sum;                       // exclusive chunk base
            for (int blk = lo; blk < hi; blk++) {
                g_excl[blk * NBINS + bin] = run;
                run += g_agg[blk * NBINS + bin];
            }
            int tot = __shfl_sync(FULLMASK, v, 31);  // bin total
            if (lane == 0) g_totals[bin] = tot;
        }
        __syncthreads();
        __threadfence();
        if (tid == 0) {
            *(volatile unsigned*)&g_totFlag  = etag;
            *(volatile unsigned*)&g_scanDone = etag;
        }
        return;
    }

    // ---- tail-zero tickets -------------------------------------------------
    if (vbid >= nblocks) {
        if (tid == 0) {
            while (*(volatile unsigned*)&g_totFlag < etag) { }
        }
        __syncthreads();
        __threadfence();
        int z   = vbid - nblocks;            // 0..ZBLOCKS-1
        int bin = z >> 3;                    // 8 tickets per bin
        int sub = z & 7;
        int c   = min(g_totals[bin], max_length);
        size_t start  = ((size_t)bin * max_length + c) * 16;
        size_t end    = ((size_t)(bin + 1) * max_length) * 16;
        size_t stride = (size_t)8 * THREADS;
        float4 zf = make_float4(0.f, 0.f, 0.f, 0.f);
        for (size_t i = start + (size_t)sub * THREADS + tid; i < end; i += stride)
            out[i] = zf;
        return;
    }

    // ---- scatter tickets ---------------------------------------------------
    int base = vbid * PPB;
    int cnt  = min(PPB, n - base);

    // coalesced load of b values into smem (only read of inds)
    for (int j = tid; j < cnt; j += THREADS)
        s_b[j] = (uint8_t)(inds4[base + j].x & (NBINS - 1));
    __syncthreads();

    // per-thread packed counts over contiguous ITEMS (2 bins / word, 16-bit)
    uint32_t c[4] = {0, 0, 0, 0};
    int lo = tid * ITEMS;
#pragma unroll
    for (int k = 0; k < ITEMS; k++) {
        int j = lo + k;
        if (j < cnt) {
            int b = s_b[j];
            c[b >> 1] += (1u << ((b & 1) * 16));
        }
    }

    // warp-level inclusive scan of the packed vector
    uint32_t inc[4];
#pragma unroll
    for (int i = 0; i < 4; i++) inc[i] = c[i];
#pragma unroll
    for (int off = 1; off < 32; off <<= 1) {
#pragma unroll
        for (int i = 0; i < 4; i++) {
            uint32_t v = __shfl_up_sync(FULLMASK, inc[i], off);
            if (lane >= off) inc[i] += v;
        }
    }
    if (lane == 31) {
#pragma unroll
        for (int i = 0; i < 4; i++) s_wtot[wid][i] = inc[i];
    }
    __syncthreads();

    if (wid == 0) {
        // ---- warp 0: publish aggregate, inter-warp scan, wait for scanner --
        int agg = 0;
        if (lane < NBINS) {
            int w4 = lane >> 1, sh = (lane & 1) * 16;
#pragma unroll
            for (int w = 0; w < THREADS / 32; w++)
                agg += (int)((s_wtot[w][w4] >> sh) & 0xFFFFu);
        }
        if (lane < NBINS) g_agg[vbid * NBINS + lane] = agg;
        __threadfence();
        if (lane == 0) *(volatile unsigned*)&g_flag[vbid] = etag;

        // inter-warp exclusive scan of warp totals (overlaps the spin wait)
        {
            int word = lane >> 3;
            int w    = lane & 7;
            uint32_t orig = s_wtot[w][word];
            uint32_t v = orig;
#pragma unroll
            for (int off = 1; off < 8; off <<= 1) {
                uint32_t tt = __shfl_up_sync(FULLMASK, v, off);
                if ((lane & 7) >= off) v += tt;
            }
            s_wexc[w][word] = v - orig;
        }

        // wait for the global scan, then fetch this block's bases
        if (lane == 0) {
            while (*(volatile unsigned*)&g_scanDone < etag) { }
        }
        __syncwarp();
        __threadfence();
        if (lane < NBINS) s_off[lane] = g_excl[vbid * NBINS + lane];
    } else {
        // ---- warps 1-7: prefetch head of feat chunk into L2 while waiting --
        // Descending line order => first-used lines are most recently touched.
        const char* chunk = (const char*)(feat + (size_t)base * 16);
        int pt = tid - 32;                       // 0..223
        int maxLines = min(PF_LINES, (cnt * 16) / 8);   // 128B lines in chunk
        for (int i = maxLines - 1 - pt; i >= 0; i -= (THREADS - 32)) {
            asm volatile("prefetch.global.L2 [%0];" :: "l"(chunk + (size_t)i * 128));
        }
    }
    __syncthreads();

    // exclusive prefix for this thread
    uint32_t p[4];
#pragma unroll
    for (int i = 0; i < 4; i++) p[i] = inc[i] - c[i] + s_wexc[wid][i];

    // replay: assign stable ranks, compute destination rows
#pragma unroll
    for (int k = 0; k < ITEMS; k++) {
        int j = lo + k;
        if (j < cnt) {
            int b   = s_b[j];
            int sh  = (b & 1) * 16;
            int w   = b >> 1;
            int pos = s_off[b] + (int)((p[w] >> sh) & 0xFFFFu);
            p[w] += (1u << sh);
            s_dst[j] = (pos < max_length) ? (b * max_length + pos) : -1;
        }
    }
    __syncthreads();

    // cooperative copy: 16 threads per point, one float4 lane each (256B rows)
    int group = tid >> 4;
    int flane = tid & 15;
#pragma unroll 4
    for (int j = group; j < cnt; j += 16) {
        int d = s_dst[j];
        float4 v = feat[(size_t)(base + j) * 16 + flane];
        if (d >= 0)
            out[(size_t)d * 16 + flane] = v;
    }
}

// ---------------------------------------------------------------------------
extern "C" void kernel_launch(void* const* d_in, const int* in_sizes, int n_in,
                              void* d_out, int out_size) {
    const int4*   inds4 = (const int4*)d_in[0];
    const float4* feat  = (const float4*)d_in[1];
    float4*       out   = (float4*)d_out;

    int n = in_sizes[0] / 4;                  // points (inds is [N,4])
    int C = in_sizes[1] / n;                  // 64
    int max_length = out_size / (NBINS * C);  // 256000

    int nblocks = (n + PPB - 1) / PPB;        // 1117
    if (nblocks > MAX_BLOCKS) nblocks = MAX_BLOCKS;
    int gridTotal = nblocks + ZBLOCKS + 1;    // 1182 (scatter + zero + scanner)

    fused_kernel<<<gridTotal, THREADS>>>(inds4, feat, out,
                                         n, max_length, nblocks, gridTotal);
}

// round 16
// speedup vs baseline: 1.0153x; 1.0109x over previous
#include <cuda_runtime.h>
#include <stdint.h>

// Fixed-shape bench: N=2e6 points, C=64 floats, bs=8, max_length=out/(8*64).
#define NBINS      8
#define THREADS    256
#define PPB        1792                 // points per block -> grid fills 8 CTA/SM
#define ITEMS      (PPB / THREADS)      // 7 contiguous points per thread
#define MAX_BLOCKS 8192
#define ZBLOCKS    64                   // tail-zero tickets
#define FULLMASK   0xFFFFFFFFu
#define PF_LINES   512                  // 64KB/block (~74MB chip-wide): measured optimum; 640 thrashes L2

// Persistent scratch — never reset. Epoch-tagged: 32-bit ticket increases
// monotonically; epoch = ticket / gridTotal; all waits compare >= epoch+1,
// so stale values from earlier replays are strictly smaller.
__device__ unsigned g_ticket;                    // zero-init at load
__device__ unsigned g_flag[MAX_BLOCKS];          // epoch+1 when block agg ready
__device__ int      g_agg [MAX_BLOCKS * NBINS];
__device__ int      g_excl[MAX_BLOCKS * NBINS];  // per-block per-bin exclusive base
__device__ unsigned g_scanDone;                  // epoch+1 when g_excl ready
__device__ unsigned g_totFlag;                   // epoch+1 when totals ready
__device__ int      g_totals[NBINS];

// ---------------------------------------------------------------------------
// Single launch, three roles by ticket:
//   vbid <  nblocks                : scatter block (publish agg, wait, copy)
//   nblocks <= vbid < nblocks+ZB   : tail-zero block
//   vbid == nblocks+ZB (last)      : scanner (global 8-bin exclusive scan)
// Whole grid resident in one wave: grid=1182 <= 8 CTA/SM * 148 SMs = 1184
// (152 SMs on GB300 -> 1216), launch_bounds pins regs<=32.
// While warp 0 waits on the scanner, warps 1-7 prefetch the head of the
// block's feat chunk into L2 (descending order; LRU keeps first-used lines),
// converting the otherwise DRAM-idle scan window into useful read traffic.
// ---------------------------------------------------------------------------
__global__ __launch_bounds__(THREADS, 8)
void fused_kernel(const int4* __restrict__ inds4,
                  const float4* __restrict__ feat,
                  float4* __restrict__ out,
                  int n, int max_length, int nblocks, int gridTotal) {
    __shared__ unsigned s_ticket;
    __shared__ uint8_t  s_b[PPB];
    __shared__ int      s_dst[PPB];
    __shared__ uint32_t s_wtot[THREADS / 32][4];   // warp-inclusive totals (packed)
    __shared__ uint32_t s_wexc[THREADS / 32][4];   // warp exclusive offsets
    __shared__ int      s_off[NBINS];              // this block's per-bin base

    int tid  = threadIdx.x;
    int wid  = tid >> 5;
    int lane = tid & 31;

    if (tid == 0) s_ticket = atomicAdd(&g_ticket, 1u);
    __syncthreads();
    unsigned t     = s_ticket;
    unsigned epoch = t / (unsigned)gridTotal;
    int      vbid  = (int)(t - epoch * (unsigned)gridTotal);
    unsigned etag  = epoch + 1u;

    // ---- scanner ticket (last) --------------------------------------------
    if (vbid == nblocks + ZBLOCKS) {
        for (int blk = tid; blk < nblocks; blk += THREADS)
            while (*(volatile unsigned*)&g_flag[blk] < etag) { }
        __syncthreads();
        __threadfence();
        if (wid < NBINS) {
            int bin = wid;
            int per = (nblocks + 31) / 32;
            int lo  = lane * per;
            int hi  = min(lo + per, nblocks);
            int sum = 0;
            for (int blk = lo; blk < hi; blk++)
                sum += g_agg[blk * NBINS + bin];
            int v = sum;
#pragma unroll
            for (int off = 1; off < 32; off <<= 1) {
                int tt = __shfl_up_sync(FULLMASK, v, off);
                if (lane >= off) v += tt;
            }
            int run = v - sum;                       // exclusive chunk base
            for (int blk = lo; blk < hi; blk++) {
                g_excl[blk * NBINS + bin] = run;
                run += g_agg[blk * NBINS + bin];
            }
            int tot = __shfl_sync(FULLMASK, v, 31);  // bin total
            if (lane == 0) g_totals[bin] = tot;
        }
        __syncthreads();
        __threadfence();
        if (tid == 0) {
            *(volatile unsigned*)&g_totFlag  = etag;
            *(volatile unsigned*)&g_scanDone = etag;
        }
        return;
    }

    // ---- tail-zero tickets -------------------------------------------------
    if (vbid >= nblocks) {
        if (tid == 0) {
            while (*(volatile unsigned*)&g_totFlag < etag) { }
        }
        __syncthreads();
        __threadfence();
        int z   = vbid - nblocks;            // 0..ZBLOCKS-1
        int bin = z >> 3;                    // 8 tickets per bin
        int sub = z & 7;
        int c   = min(g_totals[bin], max_length);
        size_t start  = ((size_t)bin * max_length + c) * 16;
        size_t end    = ((size_t)(bin + 1) * max_length) * 16;
        size_t stride = (size_t)8 * THREADS;
        float4 zf = make_float4(0.f, 0.f, 0.f, 0.f);
        for (size_t i = start + (size_t)sub * THREADS + tid; i < end; i += stride)
            out[i] = zf;
        return;
    }

    // ---- scatter tickets ---------------------------------------------------
    int base = vbid * PPB;
    int cnt  = min(PPB, n - base);

    // coalesced load of b values into smem (only read of inds)
    for (int j = tid; j < cnt; j += THREADS)
        s_b[j] = (uint8_t)(inds4[base + j].x & (NBINS - 1));
    __syncthreads();

    // per-thread packed counts over contiguous ITEMS (2 bins / word, 16-bit)
    uint32_t c[4] = {0, 0, 0, 0};
    int lo = tid * ITEMS;
#pragma unroll
    for (int k = 0; k < ITEMS; k++) {
        int j = lo + k;
        if (j < cnt) {
            int b = s_b[j];
            c[b >> 1] += (1u << ((b & 1) * 16));
        }
    }

    // warp-level inclusive scan of the packed vector
    uint32_t inc[4];
#pragma unroll
    for (int i = 0; i < 4; i++) inc[i] = c[i];
#pragma unroll
    for (int off = 1; off < 32; off <<= 1) {
#pragma unroll
        for (int i = 0; i < 4; i++) {
            uint32_t v = __shfl_up_sync(FULLMASK, inc[i], off);
            if (lane >= off) inc[i] += v;
        }
    }
    if (lane == 31) {
#pragma unroll
        for (int i = 0; i < 4; i++) s_wtot[wid][i] = inc[i];
    }
    __syncthreads();

    if (wid == 0) {
        // ---- warp 0: publish aggregate, inter-warp scan, wait for scanner --
        int agg = 0;
        if (lane < NBINS) {
            int w4 = lane >> 1, sh = (lane & 1) * 16;
#pragma unroll
            for (int w = 0; w < THREADS / 32; w++)
                agg += (int)((s_wtot[w][w4] >> sh) & 0xFFFFu);
        }
        if (lane < NBINS) g_agg[vbid * NBINS + lane] = agg;
        __threadfence();
        if (lane == 0) *(volatile unsigned*)&g_flag[vbid] = etag;

        // inter-warp exclusive scan of warp totals (overlaps the spin wait)
        {
            int word = lane >> 3;
            int w    = lane & 7;
            uint32_t orig = s_wtot[w][word];
            uint32_t v = orig;
#pragma unroll
            for (int off = 1; off < 8; off <<= 1) {
                uint32_t tt = __shfl_up_sync(FULLMASK, v, off);
                if ((lane & 7) >= off) v += tt;
            }
            s_wexc[w][word] = v - orig;
        }

        // wait for the global scan, then fetch this block's bases
        if (lane == 0) {
            while (*(volatile unsigned*)&g_scanDone < etag) { }
        }
        __syncwarp();
        __threadfence();
        if (lane < NBINS) s_off[lane] = g_excl[vbid * NBINS + lane];
    } else {
        // ---- warps 1-7: prefetch head of feat chunk into L2 while waiting --
        // Descending line order => first-used lines are most recently touched.
        const char* chunk = (const char*)(feat + (size_t)base * 16);
        int pt = tid - 32;                       // 0..223
        int maxLines = min(PF_LINES, (cnt * 16) / 8);   // 128B lines in chunk
        for (int i = maxLines - 1 - pt; i >= 0; i -= (THREADS - 32)) {
            asm volatile("prefetch.global.L2 [%0];" :: "l"(chunk + (size_t)i * 128));
        }
    }
    __syncthreads();

    // exclusive prefix for this thread
    uint32_t p[4];
#pragma unroll
    for (int i = 0; i < 4; i++) p[i] = inc[i] - c[i] + s_wexc[wid][i];

    // replay: assign stable ranks, compute destination rows
#pragma unroll
    for (int k = 0; k < ITEMS; k++) {
        int j = lo + k;
        if (j < cnt) {
            int b   = s_b[j];
            int sh  = (b & 1) * 16;
            int w   = b >> 1;
            int pos = s_off[b] + (int)((p[w] >> sh) & 0xFFFFu);
            p[w] += (1u << sh);
            s_dst[j] = (pos < max_length) ? (b * max_length + pos) : -1;
        }
    }
    __syncthreads();

    // cooperative copy: 16 threads per point, one float4 lane each (256B rows)
    int group = tid >> 4;
    int flane = tid & 15;
#pragma unroll 4
    for (int j = group; j < cnt; j += 16) {
        int d = s_dst[j];
        float4 v = feat[(size_t)(base + j) * 16 + flane];
        if (d >= 0)
            out[(size_t)d * 16 + flane] = v;
    }
}

// ---------------------------------------------------------------------------
extern "C" void kernel_launch(void* const* d_in, const int* in_sizes, int n_in,
                              void* d_out, int out_size) {
    const int4*   inds4 = (const int4*)d_in[0];
    const float4* feat  = (const float4*)d_in[1];
    float4*       out   = (float4*)d_out;

    int n = in_sizes[0] / 4;                  // points (inds is [N,4])
    int C = in_sizes[1] / n;                  // 64
    int max_length = out_size / (NBINS * C);  // 256000

    int nblocks = (n + PPB - 1) / PPB;        // 1117
    if (nblocks > MAX_BLOCKS) nblocks = MAX_BLOCKS;
    int gridTotal = nblocks + ZBLOCKS + 1;    // 1182 (scatter + zero + scanner)

    fused_kernel<<<gridTotal, THREADS>>>(inds4, feat, out,
                                         n, max_length, nblocks, gridTotal);
}